// round 5
// baseline (speedup 1.0000x reference)
#include <cuda_runtime.h>
#include <cuda_bf16.h>
#include <cstdint>

#define N_CAND 65536
#define HID 1024
#define C_CH 256
#define HW 361

#define SA_VAL (8.0f / 127.0f)
#define QA_VAL (127.0f / 8.0f)

// ---------------- scratch ----------------
__device__ float g_pft[HW * C_CH];
__device__ float g_gp[C_CH];
__device__ float g_b1eff[HID];
__device__ float g_P[2 * HW * HID];          // [go/to][pos][1024] fp32
__device__ int   g_go[N_CAND], g_to[N_CAND];
__device__ __nv_bfloat16 g_chi[N_CAND * 64], g_clo[N_CAND * 64];
__device__ __nv_bfloat16 g_Wchi[HID * 64],  g_Wclo[HID * 64];        // W1c^T [n][k]
__device__ char g_hq1[(size_t)N_CAND * HID], g_hq2[(size_t)N_CAND * HID];  // h1 int8 limbs [m][k]
__device__ char g_W2q1[HID * HID], g_W2q2[HID * HID];                // W2^T int8 limbs [n][k]
__device__ float g_sB[HID], g_isB[HID];
__device__ float g_part[8 * N_CAND];

// ---------------- helpers ----------------
__device__ __forceinline__ uint32_t smem_u32(const void* p) {
    uint32_t a;
    asm("{ .reg .u64 t; cvta.to.shared.u64 t, %1; cvt.u32.u64 %0, t; }" : "=r"(a) : "l"(p));
    return a;
}
__device__ __forceinline__ void cp16(uint32_t dst, const void* src) {
    asm volatile("cp.async.cg.shared.global [%0], [%1], 16;" :: "r"(dst), "l"(src));
}
__device__ __forceinline__ void cp_commit() { asm volatile("cp.async.commit_group;" ::: "memory"); }
template<int N> __device__ __forceinline__ void cp_wait() {
    asm volatile("cp.async.wait_group %0;" :: "n"(N) : "memory");
}
__device__ __forceinline__ void ldsm4(uint32_t* r, uint32_t a) {
    asm volatile("ldmatrix.sync.aligned.m8n8.x4.shared.b16 {%0,%1,%2,%3}, [%4];"
                 : "=r"(r[0]), "=r"(r[1]), "=r"(r[2]), "=r"(r[3]) : "r"(a));
}
__device__ __forceinline__ void ldsm2(uint32_t* r, uint32_t a) {
    asm volatile("ldmatrix.sync.aligned.m8n8.x2.shared.b16 {%0,%1}, [%2];"
                 : "=r"(r[0]), "=r"(r[1]) : "r"(a));
}
__device__ __forceinline__ void mma16816(float* c, const uint32_t* a, const uint32_t* b) {
    asm volatile("mma.sync.aligned.m16n8k16.row.col.f32.bf16.bf16.f32 "
                 "{%0,%1,%2,%3}, {%4,%5,%6,%7}, {%8,%9}, {%0,%1,%2,%3};"
                 : "+f"(c[0]), "+f"(c[1]), "+f"(c[2]), "+f"(c[3])
                 : "r"(a[0]), "r"(a[1]), "r"(a[2]), "r"(a[3]), "r"(b[0]), "r"(b[1]));
}
__device__ __forceinline__ void imma(int* c, const uint32_t* a, const uint32_t* b) {
    asm volatile("mma.sync.aligned.m16n8k32.row.col.s32.s8.s8.s32 "
                 "{%0,%1,%2,%3}, {%4,%5,%6,%7}, {%8,%9}, {%0,%1,%2,%3};"
                 : "+r"(c[0]), "+r"(c[1]), "+r"(c[2]), "+r"(c[3])
                 : "r"(a[0]), "r"(a[1]), "r"(a[2]), "r"(a[3]), "r"(b[0]), "r"(b[1]));
}
__device__ __forceinline__ void split_bf16(float v, __nv_bfloat16& h, __nv_bfloat16& l) {
    h = __float2bfloat16(v);
    l = __float2bfloat16(v - __bfloat162float(h));
}
__device__ __forceinline__ uint32_t pack2bf(__nv_bfloat16 a, __nv_bfloat16 b) {
    return ((uint32_t)__bfloat16_as_ushort(b) << 16) | __bfloat16_as_ushort(a);
}

// ---------------- prep kernels ----------------
__global__ void k_transpose(const float* __restrict__ pf) {
    int idx = blockIdx.x * 256 + threadIdx.x;
    int ch = idx / HW, pos = idx % HW;
    g_pft[pos * C_CH + ch] = pf[idx];
}

__global__ void k_pool() {
    int ch = threadIdx.x;
    float s = 0.f;
    for (int p = 0; p < HW; p++) s += g_pft[p * C_CH + ch];
    g_gp[ch] = s / 361.0f;
}

__global__ void k_b1eff(const float* __restrict__ W1, const float* __restrict__ b1) {
    int j = blockIdx.x * 256 + threadIdx.x;
    float s = b1[j];
    for (int c = 0; c < C_CH; c++) s += g_gp[c] * W1[(size_t)(512 + c) * HID + j];
    g_b1eff[j] = s;
}

// P tables: P[gy][pos][n] = sum_k pft[pos][k] * W1[gy*256 + k][n]
// grid (91, 2, 2): 4 positions x gy x n-half, 128 threads x 4 n
__global__ void k_ptab(const float* __restrict__ W1) {
    int p0 = blockIdx.x * 4;
    int gy = blockIdx.y;
    int n0 = blockIdx.z * 512 + threadIdx.x * 4;
    __shared__ float fs[4][C_CH];
    int tid = threadIdx.x;
    for (int idx = tid; idx < 4 * C_CH; idx += 128) {
        int r = idx >> 8, k = idx & 255;
        fs[r][k] = (p0 + r < HW) ? g_pft[(p0 + r) * C_CH + k] : 0.f;
    }
    __syncthreads();
    float4 acc[4];
    #pragma unroll
    for (int r = 0; r < 4; r++) acc[r] = make_float4(0.f, 0.f, 0.f, 0.f);
    const float* Wb = W1 + (size_t)gy * C_CH * HID;
    for (int k = 0; k < C_CH; k++) {
        float4 w = *(const float4*)&Wb[(size_t)k * HID + n0];
        #pragma unroll
        for (int r = 0; r < 4; r++) {
            float f = fs[r][k];
            acc[r].x += f * w.x; acc[r].y += f * w.y;
            acc[r].z += f * w.z; acc[r].w += f * w.w;
        }
    }
    #pragma unroll
    for (int r = 0; r < 4; r++)
        if (p0 + r < HW)
            *(float4*)&g_P[((size_t)gy * HW + p0 + r) * HID + n0] = acc[r];
}

__global__ void k_idx(const float* __restrict__ cand) {
    int i = blockIdx.x * 256 + threadIdx.x;
    const float* cf = cand + (size_t)i * 64;
    int gr = min(max((int)(cf[5] * 18.0f), 0), 18);
    int gc = min(max((int)(cf[6] * 18.0f), 0), 18);
    int tr = min(max((int)(cf[7] * 18.0f), 0), 18);
    int tc = min(max((int)(cf[8] * 18.0f), 0), 18);
    g_go[i] = gr * 19 + gc;
    g_to[i] = tr * 19 + tc;
}

__global__ void k_candsplit(const float* __restrict__ cand) {
    int idx = blockIdx.x * 256 + threadIdx.x;
    float4 v = ((const float4*)cand)[idx];
    __nv_bfloat16 h0, h1, h2, h3, l0, l1, l2, l3;
    split_bf16(v.x, h0, l0); split_bf16(v.y, h1, l1);
    split_bf16(v.z, h2, l2); split_bf16(v.w, h3, l3);
    ((uint2*)g_chi)[idx] = make_uint2(pack2bf(h0, h1), pack2bf(h2, h3));
    ((uint2*)g_clo)[idx] = make_uint2(pack2bf(l0, l1), pack2bf(l2, l3));
}

__global__ void k_wc(const float* __restrict__ W1) {
    int idx = blockIdx.x * 256 + threadIdx.x;
    int n = idx >> 6, k = idx & 63;
    __nv_bfloat16 h, l;
    split_bf16(W1[(size_t)(768 + k) * HID + n], h, l);
    g_Wchi[idx] = h; g_Wclo[idx] = l;
}

// per-column scale of W2
__global__ void k_wscale(const float* __restrict__ W2) {
    int n = blockIdx.x * 256 + threadIdx.x;
    float m = 0.f;
    for (int k = 0; k < HID; k++) m = fmaxf(m, fabsf(W2[(size_t)k * HID + n]));
    float s = m / 127.0f;
    g_sB[n] = s;
    g_isB[n] = 127.0f / m;
}

// transpose + 2-limb int8 quantize of W2: g_W2q*[n][k]
__global__ void k_wq2(const float* __restrict__ W2) {
    __shared__ float tile[32][33];
    int kt = blockIdx.y * 32, nt = blockIdx.x * 32;
    int tx = threadIdx.x, ty = threadIdx.y;
    for (int r = ty; r < 32; r += 8)
        tile[r][tx] = W2[(size_t)(kt + r) * HID + nt + tx];
    __syncthreads();
    for (int r = ty; r < 32; r += 8) {
        float inv = g_isB[nt + r];
        float t = tile[tx][r] * inv;          // in [-127, 127]
        float p1 = rintf(t);
        float p2 = rintf((t - p1) * 128.0f);
        g_W2q1[(size_t)(nt + r) * HID + kt + tx] = (char)(int)p1;
        g_W2q2[(size_t)(nt + r) * HID + kt + tx] = (char)(int)p2;
    }
}

// ---------------- GEMM1: bf16 3-term, CTA 128x128, 8 warps, K=64 ----------------
#define ROWB 80
#define OA_HI 0
#define OA_LO 10240
#define OB_HI 20480
#define OB_LO 30720
#define SSTRIDE 40960
#define SMEM_BYTES (3 * SSTRIDE)

__global__ __launch_bounds__(256, 1)
void k_mma1() {
    extern __shared__ char smem[];
    const uint32_t sb = smem_u32(smem);
    const int tid = threadIdx.x;
    const int lane = tid & 31, wid = tid >> 5;
    const int wm = wid >> 2, wn = wid & 3;
    const int mBase = blockIdx.y * 128;
    const int nBase = blockIdx.x * 128;
    const int K = 64, NC = 2;

    const int lrow = tid >> 1;
    const int lc = (tid & 1) * 2;
    const __nv_bfloat16* aHiP = g_chi + (size_t)(mBase + lrow) * K + lc * 8;
    const __nv_bfloat16* aLoP = g_clo + (size_t)(mBase + lrow) * K + lc * 8;
    const __nv_bfloat16* bHiP = g_Wchi + (size_t)(nBase + lrow) * K + lc * 8;
    const __nv_bfloat16* bLoP = g_Wclo + (size_t)(nBase + lrow) * K + lc * 8;
    const uint32_t sA = lrow * ROWB + lc * 16;

    auto load_chunk = [&](int chunk, int buf) {
        uint32_t st = sb + buf * SSTRIDE;
        int k0 = chunk * 32;
        cp16(st + OA_HI + sA,      aHiP + k0);
        cp16(st + OA_HI + sA + 16, aHiP + k0 + 8);
        cp16(st + OA_LO + sA,      aLoP + k0);
        cp16(st + OA_LO + sA + 16, aLoP + k0 + 8);
        cp16(st + OB_HI + sA,      bHiP + k0);
        cp16(st + OB_HI + sA + 16, bHiP + k0 + 8);
        cp16(st + OB_LO + sA,      bLoP + k0);
        cp16(st + OB_LO + sA + 16, bLoP + k0 + 8);
        cp_commit();
    };

    load_chunk(0, 0);
    load_chunk(1, 1);

    float acc[4][4][4];
    #pragma unroll
    for (int i = 0; i < 4; i++)
        #pragma unroll
        for (int j = 0; j < 4; j++)
            #pragma unroll
            for (int q = 0; q < 4; q++) acc[i][j][q] = 0.f;

    const uint32_t aOff = (uint32_t)((wm * 64 + (lane & 15)) * ROWB + (lane >> 4) * 16);
    const uint32_t bOff = (uint32_t)((wn * 32 + (lane & 7)) * ROWB + ((lane >> 3) & 1) * 16);

    for (int c = 0; c < NC; c++) {
        if (c == 0) cp_wait<1>(); else cp_wait<0>();
        __syncthreads();
        uint32_t st = sb + c * SSTRIDE;
        #pragma unroll
        for (int kk = 0; kk < 2; kk++) {
            uint32_t ah[4][4], al[4][4], bh[4][2], bl[4][2];
            #pragma unroll
            for (int i = 0; i < 4; i++) {
                ldsm4(ah[i], st + OA_HI + aOff + i * (16 * ROWB) + kk * 32);
                ldsm4(al[i], st + OA_LO + aOff + i * (16 * ROWB) + kk * 32);
            }
            #pragma unroll
            for (int j = 0; j < 4; j++) {
                ldsm2(bh[j], st + OB_HI + bOff + j * (8 * ROWB) + kk * 32);
                ldsm2(bl[j], st + OB_LO + bOff + j * (8 * ROWB) + kk * 32);
            }
            #pragma unroll
            for (int i = 0; i < 4; i++)
                #pragma unroll
                for (int j = 0; j < 4; j++) {
                    mma16816(acc[i][j], ah[i], bh[j]);
                    mma16816(acc[i][j], ah[i], bl[j]);
                    mma16816(acc[i][j], al[i], bh[j]);
                }
        }
        __syncthreads();
    }

    // epilogue: + P_go + P_to + b1eff, relu, quantize to int8 limbs
    int* sgo = (int*)smem;
    int* sto = (int*)(smem + 512);
    if (tid < 128) { sgo[tid] = g_go[mBase + tid]; sto[tid] = g_to[mBase + tid]; }
    __syncthreads();
    #pragma unroll
    for (int i = 0; i < 4; i++) {
        #pragma unroll
        for (int rr = 0; rr < 2; rr++) {
            int rl = wm * 64 + i * 16 + rr * 8 + (lane >> 2);
            size_t row = (size_t)(mBase + rl);
            const float* pg = g_P + (size_t)sgo[rl] * HID;
            const float* pt = g_P + (size_t)(HW + sto[rl]) * HID;
            #pragma unroll
            for (int j = 0; j < 4; j++) {
                int n = nBase + wn * 32 + j * 8 + 2 * (lane & 3);
                float v0 = acc[i][j][rr * 2 + 0] + pg[n] + pt[n] + g_b1eff[n];
                float v1 = acc[i][j][rr * 2 + 1] + pg[n + 1] + pt[n + 1] + g_b1eff[n + 1];
                v0 = fmaxf(v0, 0.f); v1 = fmaxf(v1, 0.f);
                float t0 = fminf(v0 * QA_VAL, 127.0f);
                float t1 = fminf(v1 * QA_VAL, 127.0f);
                float q1a = rintf(t0), q1b = rintf(t1);
                float q2a = rintf((t0 - q1a) * 128.0f);
                float q2b = rintf((t1 - q1b) * 128.0f);
                char2 c1 = make_char2((char)(int)q1a, (char)(int)q1b);
                char2 c2 = make_char2((char)(int)q2a, (char)(int)q2b);
                *(char2*)(g_hq1 + row * HID + n) = c1;
                *(char2*)(g_hq2 + row * HID + n) = c2;
            }
        }
    }
}

// ---------------- GEMM2: int8 2-limb, CTA 128x128, 8 warps, kc=64, 3 stages ----------------
#define I_OA1 0
#define I_OA2 10240
#define I_OB1 20480
#define I_OB2 30720

__global__ __launch_bounds__(256, 1)
void k_mma2(const float* __restrict__ b2, const float* __restrict__ w3) {
    extern __shared__ char smem[];
    const uint32_t sb = smem_u32(smem);
    const int tid = threadIdx.x;
    const int lane = tid & 31, wid = tid >> 5;
    const int wm = wid >> 2, wn = wid & 3;
    const int mBase = blockIdx.y * 128;
    const int nBase = blockIdx.x * 128;
    const int NC = 16;   // 1024 / 64

    const int lrow = tid >> 1;
    const int seg = (tid & 1) * 32;
    const char* a1P = g_hq1 + (size_t)(mBase + lrow) * HID + seg;
    const char* a2P = g_hq2 + (size_t)(mBase + lrow) * HID + seg;
    const char* b1P = g_W2q1 + (size_t)(nBase + lrow) * HID + seg;
    const char* b2P = g_W2q2 + (size_t)(nBase + lrow) * HID + seg;
    const uint32_t sA = lrow * ROWB + seg;

    auto load_chunk = [&](int chunk, int buf) {
        uint32_t st = sb + buf * SSTRIDE;
        int k0 = chunk * 64;
        cp16(st + I_OA1 + sA,      a1P + k0);
        cp16(st + I_OA1 + sA + 16, a1P + k0 + 16);
        cp16(st + I_OA2 + sA,      a2P + k0);
        cp16(st + I_OA2 + sA + 16, a2P + k0 + 16);
        cp16(st + I_OB1 + sA,      b1P + k0);
        cp16(st + I_OB1 + sA + 16, b1P + k0 + 16);
        cp16(st + I_OB2 + sA,      b2P + k0);
        cp16(st + I_OB2 + sA + 16, b2P + k0 + 16);
        cp_commit();
    };

    load_chunk(0, 0);
    load_chunk(1, 1);
    load_chunk(2, 2);

    int acc1[4][4][4], accm[4][4][4];
    #pragma unroll
    for (int i = 0; i < 4; i++)
        #pragma unroll
        for (int j = 0; j < 4; j++)
            #pragma unroll
            for (int q = 0; q < 4; q++) { acc1[i][j][q] = 0; accm[i][j][q] = 0; }

    const uint32_t aOff = (uint32_t)((wm * 64 + (lane & 15)) * ROWB + (lane >> 4) * 16);
    const uint32_t bOff = (uint32_t)((wn * 32 + (lane & 7)) * ROWB + ((lane >> 3) & 1) * 16);

    int buf = 0;
    for (int c = 0; c < NC; c++) {
        if (NC - 1 - c >= 2) cp_wait<2>();
        else if (NC - 1 - c == 1) cp_wait<1>();
        else cp_wait<0>();
        __syncthreads();

        uint32_t st = sb + buf * SSTRIDE;
        #pragma unroll
        for (int ks = 0; ks < 2; ks++) {
            uint32_t a1f[4][4], a2f[4][4], b1f[4][2], b2f[4][2];
            #pragma unroll
            for (int i = 0; i < 4; i++) {
                ldsm4(a1f[i], st + I_OA1 + aOff + i * (16 * ROWB) + ks * 32);
                ldsm4(a2f[i], st + I_OA2 + aOff + i * (16 * ROWB) + ks * 32);
            }
            #pragma unroll
            for (int j = 0; j < 4; j++) {
                ldsm2(b1f[j], st + I_OB1 + bOff + j * (8 * ROWB) + ks * 32);
                ldsm2(b2f[j], st + I_OB2 + bOff + j * (8 * ROWB) + ks * 32);
            }
            #pragma unroll
            for (int i = 0; i < 4; i++)
                #pragma unroll
                for (int j = 0; j < 4; j++) {
                    imma(acc1[i][j], a1f[i], b1f[j]);
                    imma(accm[i][j], a1f[i], b2f[j]);
                    imma(accm[i][j], a2f[i], b1f[j]);
                }
        }
        __syncthreads();
        if (c + 3 < NC) load_chunk(c + 3, buf);
        buf = (buf + 1 == 3) ? 0 : buf + 1;
    }
    __syncthreads();

    // epilogue: value = SA*sB[n]*(acc1 + accm/128); relu(+b2)*w3; reduce per row
    float* red = (float*)smem;
    #pragma unroll
    for (int i = 0; i < 4; i++) {
        float s0 = 0.f, s1 = 0.f;
        #pragma unroll
        for (int j = 0; j < 4; j++) {
            int n = nBase + wn * 32 + j * 8 + 2 * (lane & 3);
            float sc0 = SA_VAL * g_sB[n], sc1 = SA_VAL * g_sB[n + 1];
            float bb0 = b2[n], bb1 = b2[n + 1];
            float w0 = w3[n], w1 = w3[n + 1];
            float v0 = sc0 * ((float)acc1[i][j][0] + (float)accm[i][j][0] * 0.0078125f);
            float v1 = sc1 * ((float)acc1[i][j][1] + (float)accm[i][j][1] * 0.0078125f);
            float v2 = sc0 * ((float)acc1[i][j][2] + (float)accm[i][j][2] * 0.0078125f);
            float v3 = sc1 * ((float)acc1[i][j][3] + (float)accm[i][j][3] * 0.0078125f);
            s0 += fmaxf(v0 + bb0, 0.f) * w0 + fmaxf(v1 + bb1, 0.f) * w1;
            s1 += fmaxf(v2 + bb0, 0.f) * w0 + fmaxf(v3 + bb1, 0.f) * w1;
        }
        s0 += __shfl_xor_sync(0xffffffffu, s0, 1);
        s0 += __shfl_xor_sync(0xffffffffu, s0, 2);
        s1 += __shfl_xor_sync(0xffffffffu, s1, 1);
        s1 += __shfl_xor_sync(0xffffffffu, s1, 2);
        if ((lane & 3) == 0) {
            int rl = wm * 64 + i * 16 + (lane >> 2);
            red[wn * 128 + rl] = s0;
            red[wn * 128 + rl + 8] = s1;
        }
    }
    __syncthreads();
    if (tid < 128) {
        float s = red[tid] + red[128 + tid] + red[256 + tid] + red[384 + tid];
        g_part[(size_t)blockIdx.x * N_CAND + mBase + tid] = s;
    }
}

__global__ void k_reduce(const float* __restrict__ b3, float* __restrict__ out) {
    int n = blockIdx.x * 256 + threadIdx.x;
    float s = b3[0];
    #pragma unroll
    for (int t = 0; t < 8; t++) s += g_part[(size_t)t * N_CAND + n];
    out[n] = s;
}

// ---------------- launch ----------------
extern "C" void kernel_launch(void* const* d_in, const int* in_sizes, int n_in,
                              void* d_out, int out_size) {
    const float* pf   = (const float*)d_in[0];
    const float* cand = (const float*)d_in[1];
    const float* W1   = (const float*)d_in[2];
    const float* b1   = (const float*)d_in[3];
    const float* W2   = (const float*)d_in[4];
    const float* b2   = (const float*)d_in[5];
    const float* W3   = (const float*)d_in[6];
    const float* b3   = (const float*)d_in[7];
    float* out = (float*)d_out;

    k_transpose<<<(C_CH * HW) / 256, 256>>>(pf);
    k_pool<<<1, 256>>>();
    k_b1eff<<<HID / 256, 256>>>(W1, b1);
    k_ptab<<<dim3(91, 2, 2), 128>>>(W1);
    k_idx<<<N_CAND / 256, 256>>>(cand);
    k_candsplit<<<(N_CAND * 16) / 256, 256>>>(cand);
    k_wc<<<(HID * 64) / 256, 256>>>(W1);
    k_wscale<<<HID / 256, 256>>>(W2);
    k_wq2<<<dim3(32, 32), dim3(32, 8)>>>(W2);

    cudaFuncSetAttribute(k_mma1, cudaFuncAttributeMaxDynamicSharedMemorySize, SMEM_BYTES);
    cudaFuncSetAttribute(k_mma2, cudaFuncAttributeMaxDynamicSharedMemorySize, SMEM_BYTES);

    dim3 g(HID / 128, N_CAND / 128);   // (8, 512)
    k_mma1<<<g, 256, SMEM_BYTES>>>();
    k_mma2<<<g, 256, SMEM_BYTES>>>(b2, W3);
    k_reduce<<<N_CAND / 256, 256>>>(b3, out);
}

// round 8
// speedup vs baseline: 4.1680x; 4.1680x over previous
#include <cuda_runtime.h>
#include <cuda_fp16.h>
#include <cstdint>

#define N_CAND 65536
#define HID 1024
#define C_CH 256
#define HW 361

// ---------------- scratch ----------------
__device__ float g_b1eff[HID];
__device__ float g_P[2 * HW * HID];          // [go/to][pos][1024] fp32
__device__ int   g_go[N_CAND], g_to[N_CAND];
__device__ __half g_c16[N_CAND * 64];        // cand feats fp16 [m][64]
__device__ __half g_Wc16[HID * 64];          // W1c^T [n][64]
__device__ __half g_W216[HID * HID];         // W2^T  [n][1024]
__device__ __half g_h116[(size_t)N_CAND * HID];
__device__ float g_part[8 * N_CAND];

// ---------------- helpers ----------------
__device__ __forceinline__ uint32_t smem_u32(const void* p) {
    uint32_t a;
    asm("{ .reg .u64 t; cvta.to.shared.u64 t, %1; cvt.u32.u64 %0, t; }" : "=r"(a) : "l"(p));
    return a;
}
__device__ __forceinline__ void cp16(uint32_t dst, const void* src) {
    asm volatile("cp.async.cg.shared.global [%0], [%1], 16;" :: "r"(dst), "l"(src));
}
__device__ __forceinline__ void cp_commit() { asm volatile("cp.async.commit_group;" ::: "memory"); }
template<int N> __device__ __forceinline__ void cp_wait() {
    asm volatile("cp.async.wait_group %0;" :: "n"(N) : "memory");
}
__device__ __forceinline__ void ldsm4(uint32_t* r, uint32_t a) {
    asm volatile("ldmatrix.sync.aligned.m8n8.x4.shared.b16 {%0,%1,%2,%3}, [%4];"
                 : "=r"(r[0]), "=r"(r[1]), "=r"(r[2]), "=r"(r[3]) : "r"(a));
}
__device__ __forceinline__ void ldsm2(uint32_t* r, uint32_t a) {
    asm volatile("ldmatrix.sync.aligned.m8n8.x2.shared.b16 {%0,%1}, [%2];"
                 : "=r"(r[0]), "=r"(r[1]) : "r"(a));
}
__device__ __forceinline__ void mmaf16(float* c, const uint32_t* a, const uint32_t* b) {
    asm volatile("mma.sync.aligned.m16n8k16.row.col.f32.f16.f16.f32 "
                 "{%0,%1,%2,%3}, {%4,%5,%6,%7}, {%8,%9}, {%0,%1,%2,%3};"
                 : "+f"(c[0]), "+f"(c[1]), "+f"(c[2]), "+f"(c[3])
                 : "r"(a[0]), "r"(a[1]), "r"(a[2]), "r"(a[3]), "r"(b[0]), "r"(b[1]));
}
__device__ __forceinline__ uint32_t pack2h(__half a, __half b) {
    return ((uint32_t)__half_as_ushort(b) << 16) | __half_as_ushort(a);
}

// ---------------- prep kernels ----------------
// single block: global pool (from raw pf, channel-major) then b1eff
__global__ void k_pool_b1(const float* __restrict__ pf,
                          const float* __restrict__ W1, const float* __restrict__ b1) {
    __shared__ float sgp[C_CH];
    int tid = threadIdx.x;   // 256
    const float* row = pf + (size_t)tid * HW;
    float s = 0.f;
    for (int p = 0; p < HW; p++) s += row[p];
    sgp[tid] = s / 361.0f;
    __syncthreads();
    int j = tid * 4;
    float4 acc = *(const float4*)&b1[j];
    for (int c = 0; c < C_CH; c++) {
        float g = sgp[c];
        float4 w = *(const float4*)&W1[(size_t)(512 + c) * HID + j];
        acc.x += g * w.x; acc.y += g * w.y; acc.z += g * w.z; acc.w += g * w.w;
    }
    *(float4*)&g_b1eff[j] = acc;
}

// P tables: P[gy][pos][n] = sum_k pf[k][pos] * W1[gy*256 + k][n]
// grid (91, 2, 2): 4 positions x gy x n-half; 128 threads x 4 n
__global__ void k_ptab(const float* __restrict__ pf, const float* __restrict__ W1) {
    int p0 = blockIdx.x * 4;
    int gy = blockIdx.y;
    int n0 = blockIdx.z * 512 + threadIdx.x * 4;
    __shared__ float fs[4][C_CH];
    int tid = threadIdx.x;
    for (int idx = tid; idx < 4 * C_CH; idx += 128) {
        int r = idx >> 8, k = idx & 255;
        fs[r][k] = (p0 + r < HW) ? pf[(size_t)k * HW + p0 + r] : 0.f;
    }
    __syncthreads();
    float4 acc[4];
    #pragma unroll
    for (int r = 0; r < 4; r++) acc[r] = make_float4(0.f, 0.f, 0.f, 0.f);
    const float* Wb = W1 + (size_t)gy * C_CH * HID;
    for (int k = 0; k < C_CH; k++) {
        float4 w = *(const float4*)&Wb[(size_t)k * HID + n0];
        #pragma unroll
        for (int r = 0; r < 4; r++) {
            float f = fs[r][k];
            acc[r].x += f * w.x; acc[r].y += f * w.y;
            acc[r].z += f * w.z; acc[r].w += f * w.w;
        }
    }
    #pragma unroll
    for (int r = 0; r < 4; r++)
        if (p0 + r < HW)
            *(float4*)&g_P[((size_t)gy * HW + p0 + r) * HID + n0] = acc[r];
}

// fused: cand feats -> fp16, and go/to index decode
__global__ void k_cand(const float* __restrict__ cand) {
    int idx = blockIdx.x * 256 + threadIdx.x;    // over N_CAND*16 float4s
    float4 v = ((const float4*)cand)[idx];
    ((uint2*)g_c16)[idx] = make_uint2(pack2h(__float2half(v.x), __float2half(v.y)),
                                      pack2h(__float2half(v.z), __float2half(v.w)));
    if ((idx & 15) == 1) {
        int i = idx >> 4;
        // v = cf[4..7]
        int gr = min(max((int)(v.y * 18.0f), 0), 18);
        int gc = min(max((int)(v.z * 18.0f), 0), 18);
        int tr = min(max((int)(v.w * 18.0f), 0), 18);
        float f8 = cand[(size_t)i * 64 + 8];
        int tc = min(max((int)(f8 * 18.0f), 0), 18);
        g_go[i] = gr * 19 + gc;
        g_to[i] = tr * 19 + tc;
    }
}

// fused: W2^T fp16 convert (y<32) + Wc fp16 (y==32)
__global__ void k_wcvt(const float* __restrict__ W2, const float* __restrict__ W1) {
    int tid = threadIdx.x;
    if (blockIdx.y < 32) {
        __shared__ float tile[32][33];
        int kt = blockIdx.y * 32, nt = blockIdx.x * 32;
        int tx = tid & 31, ty = tid >> 5;
        for (int r = ty; r < 32; r += 8)
            tile[r][tx] = W2[(size_t)(kt + r) * HID + nt + tx];
        __syncthreads();
        for (int r = ty; r < 32; r += 8)
            g_W216[(size_t)(nt + r) * HID + kt + tx] = __float2half(tile[tx][r]);
    } else {
        for (int t = 0; t < 8; t++) {
            int idx = blockIdx.x * 2048 + t * 256 + tid;
            int n = idx >> 6, k = idx & 63;
            g_Wc16[idx] = __float2half(W1[(size_t)(768 + k) * HID + n]);
        }
    }
}

// ---------------- GEMM tiles: CTA 128x128, 8 warps (2m x 4n), warp 64x32 ----------------
// per stage: A 128 rows x 32 fp16 (80B padded rows) + B same
#define ROWB 80
#define OA 0
#define OB 10240
#define SSTRIDE 20480
#define SMEM1 (2 * SSTRIDE)
#define SMEM2 (3 * SSTRIDE)

// GEMM1: h1 = relu(c16 @ Wc16^T + P_go + P_to + b1eff) -> fp16
__global__ __launch_bounds__(256, 2)
void k_mma1() {
    extern __shared__ char smem[];
    const uint32_t sb = smem_u32(smem);
    const int tid = threadIdx.x;
    const int lane = tid & 31, wid = tid >> 5;
    const int wm = wid >> 2, wn = wid & 3;
    const int mBase = blockIdx.y * 128;
    const int nBase = blockIdx.x * 128;

    const int lrow = tid >> 1;
    const int lc = (tid & 1) * 2;
    const __half* aP = g_c16 + (size_t)(mBase + lrow) * 64 + lc * 8;
    const __half* bP = g_Wc16 + (size_t)(nBase + lrow) * 64 + lc * 8;
    const uint32_t sA = lrow * ROWB + lc * 16;

    auto load_chunk = [&](int chunk, int buf) {
        uint32_t st = sb + buf * SSTRIDE;
        int k0 = chunk * 32;
        cp16(st + OA + sA,      aP + k0);
        cp16(st + OA + sA + 16, aP + k0 + 8);
        cp16(st + OB + sA,      bP + k0);
        cp16(st + OB + sA + 16, bP + k0 + 8);
        cp_commit();
    };
    load_chunk(0, 0);
    load_chunk(1, 1);

    float acc[4][4][4];
    #pragma unroll
    for (int i = 0; i < 4; i++)
        #pragma unroll
        for (int j = 0; j < 4; j++)
            #pragma unroll
            for (int q = 0; q < 4; q++) acc[i][j][q] = 0.f;

    const uint32_t aOff = (uint32_t)((wm * 64 + (lane & 15)) * ROWB + (lane >> 4) * 16);
    const uint32_t bOff = (uint32_t)((wn * 32 + (lane & 7)) * ROWB + ((lane >> 3) & 1) * 16);

    #pragma unroll
    for (int c = 0; c < 2; c++) {
        if (c == 0) cp_wait<1>(); else cp_wait<0>();
        __syncthreads();
        uint32_t st = sb + c * SSTRIDE;
        #pragma unroll
        for (int kk = 0; kk < 2; kk++) {
            uint32_t a[4][4], b[4][2];
            #pragma unroll
            for (int i = 0; i < 4; i++)
                ldsm4(a[i], st + OA + aOff + i * (16 * ROWB) + kk * 32);
            #pragma unroll
            for (int j = 0; j < 4; j++)
                ldsm2(b[j], st + OB + bOff + j * (8 * ROWB) + kk * 32);
            #pragma unroll
            for (int i = 0; i < 4; i++)
                #pragma unroll
                for (int j = 0; j < 4; j++)
                    mmaf16(acc[i][j], a[i], b[j]);
        }
        __syncthreads();
    }

    int* sgo = (int*)smem;
    int* sto = (int*)(smem + 512);
    if (tid < 128) { sgo[tid] = g_go[mBase + tid]; sto[tid] = g_to[mBase + tid]; }
    __syncthreads();
    #pragma unroll
    for (int i = 0; i < 4; i++) {
        #pragma unroll
        for (int rr = 0; rr < 2; rr++) {
            int rl = wm * 64 + i * 16 + rr * 8 + (lane >> 2);
            size_t row = (size_t)(mBase + rl);
            const float* pg = g_P + (size_t)sgo[rl] * HID;
            const float* pt = g_P + (size_t)(HW + sto[rl]) * HID;
            #pragma unroll
            for (int j = 0; j < 4; j++) {
                int n = nBase + wn * 32 + j * 8 + 2 * (lane & 3);
                float v0 = acc[i][j][rr * 2 + 0] + pg[n] + pt[n] + g_b1eff[n];
                float v1 = acc[i][j][rr * 2 + 1] + pg[n + 1] + pt[n + 1] + g_b1eff[n + 1];
                v0 = fmaxf(v0, 0.f); v1 = fmaxf(v1, 0.f);
                *(uint32_t*)&g_h116[row * HID + n] = pack2h(__float2half(v0), __float2half(v1));
            }
        }
    }
}

// GEMM2: partials = relu(h1 @ W2^T + b2) . w3 per 128-n block
__global__ __launch_bounds__(256, 2)
void k_mma2(const float* __restrict__ b2, const float* __restrict__ w3) {
    extern __shared__ char smem[];
    const uint32_t sb = smem_u32(smem);
    const int tid = threadIdx.x;
    const int lane = tid & 31, wid = tid >> 5;
    const int wm = wid >> 2, wn = wid & 3;
    const int mBase = blockIdx.y * 128;
    const int nBase = blockIdx.x * 128;
    const int NC = 32;

    const int lrow = tid >> 1;
    const int lc = (tid & 1) * 2;
    const __half* aP = g_h116 + (size_t)(mBase + lrow) * HID + lc * 8;
    const __half* bP = g_W216 + (size_t)(nBase + lrow) * HID + lc * 8;
    const uint32_t sA = lrow * ROWB + lc * 16;

    auto load_chunk = [&](int chunk, int buf) {
        uint32_t st = sb + buf * SSTRIDE;
        int k0 = chunk * 32;
        cp16(st + OA + sA,      aP + k0);
        cp16(st + OA + sA + 16, aP + k0 + 8);
        cp16(st + OB + sA,      bP + k0);
        cp16(st + OB + sA + 16, bP + k0 + 8);
        cp_commit();
    };
    load_chunk(0, 0);
    load_chunk(1, 1);
    load_chunk(2, 2);

    float acc[4][4][4];
    #pragma unroll
    for (int i = 0; i < 4; i++)
        #pragma unroll
        for (int j = 0; j < 4; j++)
            #pragma unroll
            for (int q = 0; q < 4; q++) acc[i][j][q] = 0.f;

    const uint32_t aOff = (uint32_t)((wm * 64 + (lane & 15)) * ROWB + (lane >> 4) * 16);
    const uint32_t bOff = (uint32_t)((wn * 32 + (lane & 7)) * ROWB + ((lane >> 3) & 1) * 16);

    int buf = 0;
    for (int c = 0; c < NC; c++) {
        if (NC - 1 - c >= 2) cp_wait<2>();
        else if (NC - 1 - c == 1) cp_wait<1>();
        else cp_wait<0>();
        __syncthreads();

        uint32_t st = sb + buf * SSTRIDE;
        #pragma unroll
        for (int kk = 0; kk < 2; kk++) {
            uint32_t a[4][4], b[4][2];
            #pragma unroll
            for (int i = 0; i < 4; i++)
                ldsm4(a[i], st + OA + aOff + i * (16 * ROWB) + kk * 32);
            #pragma unroll
            for (int j = 0; j < 4; j++)
                ldsm2(b[j], st + OB + bOff + j * (8 * ROWB) + kk * 32);
            #pragma unroll
            for (int i = 0; i < 4; i++)
                #pragma unroll
                for (int j = 0; j < 4; j++)
                    mmaf16(acc[i][j], a[i], b[j]);
        }
        __syncthreads();
        if (c + 3 < NC) load_chunk(c + 3, buf);
        buf = (buf + 1 == 3) ? 0 : buf + 1;
    }
    __syncthreads();

    float* red = (float*)smem;
    #pragma unroll
    for (int i = 0; i < 4; i++) {
        float s0 = 0.f, s1 = 0.f;
        #pragma unroll
        for (int j = 0; j < 4; j++) {
            int n = nBase + wn * 32 + j * 8 + 2 * (lane & 3);
            float bb0 = b2[n], bb1 = b2[n + 1];
            float w0 = w3[n], w1 = w3[n + 1];
            s0 += fmaxf(acc[i][j][0] + bb0, 0.f) * w0 + fmaxf(acc[i][j][1] + bb1, 0.f) * w1;
            s1 += fmaxf(acc[i][j][2] + bb0, 0.f) * w0 + fmaxf(acc[i][j][3] + bb1, 0.f) * w1;
        }
        s0 += __shfl_xor_sync(0xffffffffu, s0, 1);
        s0 += __shfl_xor_sync(0xffffffffu, s0, 2);
        s1 += __shfl_xor_sync(0xffffffffu, s1, 1);
        s1 += __shfl_xor_sync(0xffffffffu, s1, 2);
        if ((lane & 3) == 0) {
            int rl = wm * 64 + i * 16 + (lane >> 2);
            red[wn * 128 + rl] = s0;
            red[wn * 128 + rl + 8] = s1;
        }
    }
    __syncthreads();
    if (tid < 128) {
        float s = red[tid] + red[128 + tid] + red[256 + tid] + red[384 + tid];
        g_part[(size_t)blockIdx.x * N_CAND + mBase + tid] = s;
    }
}

__global__ void k_reduce(const float* __restrict__ b3, float* __restrict__ out) {
    int n = blockIdx.x * 256 + threadIdx.x;
    float s = b3[0];
    #pragma unroll
    for (int t = 0; t < 8; t++) s += g_part[(size_t)t * N_CAND + n];
    out[n] = s;
}

// ---------------- launch ----------------
extern "C" void kernel_launch(void* const* d_in, const int* in_sizes, int n_in,
                              void* d_out, int out_size) {
    const float* pf   = (const float*)d_in[0];
    const float* cand = (const float*)d_in[1];
    const float* W1   = (const float*)d_in[2];
    const float* b1   = (const float*)d_in[3];
    const float* W2   = (const float*)d_in[4];
    const float* b2   = (const float*)d_in[5];
    const float* W3   = (const float*)d_in[6];
    const float* b3   = (const float*)d_in[7];
    float* out = (float*)d_out;

    k_pool_b1<<<1, 256>>>(pf, W1, b1);                     // 1
    k_ptab<<<dim3(91, 2, 2), 128>>>(pf, W1);               // 2
    k_cand<<<(N_CAND * 16) / 256, 256>>>(cand);            // 3
    k_wcvt<<<dim3(32, 33), 256>>>(W2, W1);                 // 4

    cudaFuncSetAttribute(k_mma1, cudaFuncAttributeMaxDynamicSharedMemorySize, SMEM1);
    cudaFuncSetAttribute(k_mma2, cudaFuncAttributeMaxDynamicSharedMemorySize, SMEM2);

    dim3 g(HID / 128, N_CAND / 128);                       // (8, 512)
    k_mma1<<<g, 256, SMEM1>>>();                           // 5
    k_mma2<<<g, 256, SMEM2>>>(b2, W3);                     // 6  <- ncu -s5 lands here
    k_reduce<<<N_CAND / 256, 256>>>(b3, out);              // 7
}